// round 16
// baseline (speedup 1.0000x reference)
#include <cuda_runtime.h>
#include <cuda_fp16.h>
#include <math.h>
#include <stdint.h>

#define S_TOT 7681
#define C_DIM 256

// ---------------- scratch (static device globals; no allocation) ----------
__device__ float  g_off [S_TOT * C_DIM];
__device__ float  g_attn[S_TOT * 128];
__device__ float  g_tmp [S_TOT * C_DIM];
__device__ float  g_tmp2[S_TOT * C_DIM];
__device__ __half g_v16 [S_TOT * C_DIM];
__device__ __half g_x16 [S_TOT * C_DIM];
__device__ __half g_q16 [S_TOT * C_DIM];
__device__ __half g_s16 [S_TOT * C_DIM];
__device__ __half g_f16 [S_TOT * 1024];
// fp16 transposed weights, per-layer stride 753664:
// val@0, off@65536, attn@131072, out@163840, ff1@229376, ff2@491520
__device__ __half g_w16 [3 * 753664];

#define OFF_VAL  0
#define OFF_OFF  65536
#define OFF_ATTN 131072
#define OFF_OUT  163840
#define OFF_FF1  229376
#define OFF_FF2  491520
#define W_LSTR   753664

__constant__ int c_H [4] = {76, 38, 19, 10};
__constant__ int c_W [4] = {76, 38, 19, 10};
__constant__ int c_ST[4] = {0, 5776, 7220, 7581};

// ---------------- fused weight convert + transpose ------------------------
// All 6 weights x 3 layers in ONE launch. [K,N] f32 -> [N,K] f16.
struct WC {
    const float* src[6];
    int K[6], N[6], ooff[6];
    int cum[7];                 // cumulative 32x32 tile counts
};

__global__ __launch_bounds__(256) void wcvt_all_kernel(WC wc, __half* w16)
{
    __shared__ float t[32][33];
    int b = blockIdx.x;
    int g = 0;
    while (b >= wc.cum[g + 1]) g++;
    int tile = b - wc.cum[g];
    const int K = wc.K[g], N = wc.N[g];
    const int ntiles = N >> 5;
    const int k0 = (tile / ntiles) * 32;
    const int n0 = (tile % ntiles) * 32;
    const float* inl = wc.src[g] + (size_t)blockIdx.z * (size_t)K * N;
    __half* outl = w16 + (size_t)blockIdx.z * W_LSTR + wc.ooff[g];
    int tx = threadIdx.x & 31, ty = threadIdx.x >> 5;
    #pragma unroll
    for (int i = ty; i < 32; i += 8)
        t[i][tx] = inl[(size_t)(k0 + i) * N + n0 + tx];
    __syncthreads();
    #pragma unroll
    for (int i = ty; i < 32; i += 8)
        outl[(size_t)(n0 + i) * K + k0 + tx] = __float2half(t[tx][i]);
}

// ---------------- init: x = src; x16 = h(src); q16 = h(src + pos) ---------
__global__ __launch_bounds__(256) void copy2_kernel(
    float* __restrict__ x, __half* __restrict__ x16, __half* __restrict__ q16,
    const float* __restrict__ src, const float* __restrict__ pos)
{
    int i = blockIdx.x * 256 + threadIdx.x;
    float v = src[i];
    x[i] = v;
    x16[i] = __float2half(v);
    q16[i] = __float2half(v + pos[i]);
}

// ---------------- fp16 tensor-core GEMM primitives ------------------------
__device__ __forceinline__ void cp16(uint32_t s, const void* g) {
    asm volatile("cp.async.cg.shared.global [%0], [%1], 16;" :: "r"(s), "l"(g) : "memory");
}

__device__ __forceinline__ uint32_t smem_u32(const void* p) {
    return (uint32_t)__cvta_generic_to_shared(p);
}

__device__ __forceinline__ void ldsm4(uint32_t r[4], uint32_t addr) {
    asm volatile("ldmatrix.sync.aligned.m8n8.x4.shared.b16 {%0,%1,%2,%3}, [%4];"
                 : "=r"(r[0]), "=r"(r[1]), "=r"(r[2]), "=r"(r[3]) : "r"(addr));
}

__device__ __forceinline__ void mma16(float c[4], const uint32_t a[4], const uint32_t b[2]) {
    asm volatile(
        "mma.sync.aligned.m16n8k16.row.col.f32.f16.f16.f32 "
        "{%0,%1,%2,%3}, {%4,%5,%6,%7}, {%8,%9}, {%0,%1,%2,%3};"
        : "+f"(c[0]), "+f"(c[1]), "+f"(c[2]), "+f"(c[3])
        : "r"(a[0]), "r"(a[1]), "r"(a[2]), "r"(a[3]), "r"(b[0]), "r"(b[1]));
}

// Core mainloop + epilogue. BM=64 x BN=128, 256 threads (8 warps: 2M x 4N),
// warp tile 32x32, BK=32, 3-stage cp.async, ldmatrix fragment loads.
// A f16 [M,lda]; B f16 [N,ldb] (pre-transposed, k-contiguous). fp32 accumulate.
template<int RELU, int OUTH>
__device__ __forceinline__ void gemm_body(
    const __half* __restrict__ A, const __half* __restrict__ B,
    const float* __restrict__ bias, float* __restrict__ C, __half* __restrict__ C16,
    int M, int N, int K, int lda, int ldb, int m0, int n0, int use_bias,
    __half (*As)[64][40], __half (*Bs)[128][40])
{
    constexpr int BK = 32;
    constexpr int NT = 4;

    const int tid  = threadIdx.x;
    const int lane = tid & 31;
    const int wid  = tid >> 5;
    const int wm   = wid & 1;    // warp row 0..1
    const int wn   = wid >> 1;   // warp col 0..3

    float acc[2][NT][4];
    #pragma unroll
    for (int mt = 0; mt < 2; mt++)
        #pragma unroll
        for (int nt = 0; nt < NT; nt++)
            #pragma unroll
            for (int j = 0; j < 4; j++) acc[mt][nt][j] = 0.f;

    auto prefetch = [&](int buf, int k0) {
        {   // A: 64 rows x 64B
            int r = tid >> 2, c = (tid & 3) * 8;
            int gm = m0 + r; if (gm > M - 1) gm = M - 1;
            cp16(smem_u32(&As[buf][r][c]), A + (size_t)gm * lda + k0 + c);
        }
        #pragma unroll
        for (int i = 0; i < 2; i++) {   // B: 128 rows x 64B
            int f = tid + i * 256;
            int r = f >> 2, c = (f & 3) * 8;
            cp16(smem_u32(&Bs[buf][r][c]), B + (size_t)(n0 + r) * ldb + k0 + c);
        }
        asm volatile("cp.async.commit_group;" ::: "memory");
    };

    prefetch(0, 0);
    if (BK < K) prefetch(1, BK);
    else        asm volatile("cp.async.commit_group;" ::: "memory");

    const int tr = lane & 7;     // row within 8x8 tile
    const int tq = lane >> 3;    // tile index 0..3

    int buf = 0;
    for (int k0 = 0; k0 < K; k0 += BK) {
        if (k0 + BK < K) asm volatile("cp.async.wait_group 1;" ::: "memory");
        else             asm volatile("cp.async.wait_group 0;" ::: "memory");
        __syncthreads();

        if (k0 + 2 * BK < K) {
            int nb = buf + 2; if (nb >= 3) nb -= 3;
            prefetch(nb, k0 + 2 * BK);
        }

        #pragma unroll
        for (int kc = 0; kc < BK; kc += 16) {
            // A frags: tiles (m+0/k+0, m+8/k+0, m+0/k+8, m+8/k+8)
            uint32_t afr[2][4];
            #pragma unroll
            for (int mt = 0; mt < 2; mt++) {
                int row = wm * 32 + mt * 16 + tr + ((tq & 1) ? 8 : 0);
                int col = kc + ((tq >= 2) ? 8 : 0);
                ldsm4(afr[mt], smem_u32(&As[buf][row][col]));
            }
            // B frags: x4 covers two n8 groups
            uint32_t bfr[NT][2];
            #pragma unroll
            for (int j = 0; j < 2; j++) {
                int nrow = wn * 32 + j * 16 + tr + ((tq >= 2) ? 8 : 0);
                int col  = kc + ((tq & 1) ? 8 : 0);
                uint32_t r[4];
                ldsm4(r, smem_u32(&Bs[buf][nrow][col]));
                bfr[2 * j][0] = r[0]; bfr[2 * j][1] = r[1];
                bfr[2 * j + 1][0] = r[2]; bfr[2 * j + 1][1] = r[3];
            }
            #pragma unroll
            for (int mt = 0; mt < 2; mt++)
                #pragma unroll
                for (int nt = 0; nt < NT; nt++)
                    mma16(acc[mt][nt], afr[mt], bfr[nt]);
        }
        buf++; if (buf >= 3) buf = 0;
    }

    #pragma unroll
    for (int mt = 0; mt < 2; mt++) {
        int gm = m0 + wm * 32 + mt * 16 + (lane >> 2);
        #pragma unroll
        for (int nt = 0; nt < NT; nt++) {
            int gn = n0 + wn * 32 + nt * 8 + 2 * (lane & 3);
            float b0 = 0.f, b1 = 0.f;
            if (use_bias) { b0 = bias[gn]; b1 = bias[gn + 1]; }
            float v0 = acc[mt][nt][0] + b0, v1 = acc[mt][nt][1] + b1;
            float v2 = acc[mt][nt][2] + b0, v3 = acc[mt][nt][3] + b1;
            if (RELU) {
                v0 = fmaxf(v0, 0.f); v1 = fmaxf(v1, 0.f);
                v2 = fmaxf(v2, 0.f); v3 = fmaxf(v3, 0.f);
            }
            if (OUTH) {
                if (gm < M)
                    *reinterpret_cast<__half2*>(C16 + (size_t)gm * N + gn) =
                        __floats2half2_rn(v0, v1);
                if (gm + 8 < M)
                    *reinterpret_cast<__half2*>(C16 + (size_t)(gm + 8) * N + gn) =
                        __floats2half2_rn(v2, v3);
            } else {
                if (gm < M)
                    *reinterpret_cast<float2*>(C + (size_t)gm * N + gn) = make_float2(v0, v1);
                if (gm + 8 < M)
                    *reinterpret_cast<float2*>(C + (size_t)(gm + 8) * N + gn) = make_float2(v2, v3);
            }
        }
    }
}

// ff1: C16 = relu(A@B + bias) in fp16
__global__ __launch_bounds__(256) void gemm_ff1_kernel(
    const __half* __restrict__ A, const __half* __restrict__ B,
    const float* __restrict__ bias, __half* __restrict__ C16,
    int M, int N, int K)
{
    __shared__ __half As[3][64][40];
    __shared__ __half Bs[3][128][40];
    gemm_body<1, 1>(A, B, bias, nullptr, C16, M, N, K, K, K,
                    blockIdx.y * 64, blockIdx.x * 128, 1, As, Bs);
}

// Split-K=2 GEMM, one launch: kz=0 -> C0 (+bias), kz=1 -> C1.
__global__ __launch_bounds__(256) void gemm_sk2_kernel(
    const __half* __restrict__ A, const __half* __restrict__ B,
    const float* __restrict__ bias, float* __restrict__ C0, float* __restrict__ C1,
    int M, int N, int Kfull)
{
    __shared__ __half As[3][64][40];
    __shared__ __half Bs[3][128][40];
    const int kz = blockIdx.z;
    const int Kh = Kfull >> 1;
    gemm_body<0, 0>(A + (size_t)kz * Kh, B + (size_t)kz * Kh,
                    bias, kz ? C1 : C0, nullptr, M, N, Kh, Kfull, Kfull,
                    blockIdx.y * 64, blockIdx.x * 128, kz == 0, As, Bs);
}

// Fused val/off/attn: 5 N-tiles (val:2 -> fp16 out, off:2, attn:1) x 121 M-blocks.
struct MG3 {
    const __half* A[3];
    const __half* B[3];
    const float* bias[3];
    float* C[3];
    __half* C16[3];
    int N[3];
};

__global__ __launch_bounds__(256) void gemm3_kernel(MG3 mg, int M, int K)
{
    __shared__ __half As[3][64][40];
    __shared__ __half Bs[3][128][40];
    const int bx  = blockIdx.x;                       // 0..4
    const int gid = (bx < 2) ? 0 : (bx < 4) ? 1 : 2;
    const int nb  = (bx == 1 || bx == 3) ? 1 : 0;
    if (gid == 0)
        gemm_body<0, 1>(mg.A[0], mg.B[0], mg.bias[0], nullptr, mg.C16[0],
                        M, mg.N[0], K, K, K, blockIdx.y * 64, nb * 128, 1, As, Bs);
    else
        gemm_body<0, 0>(mg.A[gid], mg.B[gid], mg.bias[gid], mg.C[gid], nullptr,
                        M, mg.N[gid], K, K, K, blockIdx.y * 64, nb * 128, 1, As, Bs);
}

// ---------------- MSDA: 2 queries per 128-thread block --------------------
// Phase 1: metadata for both queries (tid = m*16 + p per query).
// Phase 2: 8 threads/head, each gathers 4 channels via uint2 (8B) loads.
__global__ __launch_bounds__(128) void msda_kernel(
    const __half* __restrict__ val16, const float* __restrict__ off,
    const float* __restrict__ attn, const float* __restrict__ vr,
    __half* __restrict__ out16)
{
    const unsigned FULL = 0xffffffffu;
    const int s0  = blockIdx.x * 2;
    const int tid = threadIdx.x;

    __shared__ uint4 smw[2][128];   // per (q, m, p): 4 corner weights as half2
    __shared__ uint4 smi[2][128];   // per (q, m, p): 4 row byte-offsets (idx*512)

    #pragma unroll
    for (int qi = 0; qi < 2; qi++) {
        const int s = s0 + qi;
        if (s < S_TOT) {
            const int m   = tid >> 4;
            const int p   = tid & 15;       // p = lvl*4 + pt
            const int lvl = p >> 2;
            const int pt  = p & 3;

            float logit = attn[(size_t)s * 128 + m * 16 + p];
            float mx = logit;
            #pragma unroll
            for (int o = 8; o > 0; o >>= 1) mx = fmaxf(mx, __shfl_xor_sync(FULL, mx, o));
            float e = expf(logit - mx);
            float sum = e;
            #pragma unroll
            for (int o = 8; o > 0; o >>= 1) sum += __shfl_xor_sync(FULL, sum, o);
            float aw = e / sum;

            int lvlS = (s >= 7581) ? 3 : (s >= 7220) ? 2 : (s >= 5776) ? 1 : 0;
            int idxS = s - c_ST[lvlS];
            int Ws = c_W[lvlS], Hs = c_H[lvlS];
            int rowS = idxS / Ws, colS = idxS - rowS * Ws;
            float bx = (colS + 0.5f) / (vr[lvlS * 2 + 0] * (float)Ws);
            float by = (rowS + 0.5f) / (vr[lvlS * 2 + 1] * (float)Hs);

            const int H = c_H[lvl], W = c_W[lvl], st = c_ST[lvl];
            float refx = bx * vr[lvl * 2 + 0];
            float refy = by * vr[lvl * 2 + 1];
            float ox = off[(size_t)s * 256 + m * 32 + lvl * 8 + pt * 2 + 0];
            float oy = off[(size_t)s * 256 + m * 32 + lvl * 8 + pt * 2 + 1];

            // match reference arithmetic order
            float lx = refx + ox / (float)W;
            float ly = refy + oy / (float)H;
            float x = lx * (float)W - 0.5f;
            float y = ly * (float)H - 0.5f;
            float x0f = floorf(x), y0f = floorf(y);
            int x0 = (int)x0f, y0 = (int)y0f;
            float dx = x - x0f, dy = y - y0f;

            bool vx0 = (x0 >= 0) & (x0 < W);
            bool vx1 = (x0 + 1 >= 0) & (x0 + 1 < W);
            bool vy0 = (y0 >= 0) & (y0 < H);
            bool vy1 = (y0 + 1 >= 0) & (y0 + 1 < H);

            float w00 = (vy0 && vx0) ? aw * (1.f - dy) * (1.f - dx) : 0.f;
            float w01 = (vy0 && vx1) ? aw * (1.f - dy) * dx          : 0.f;
            float w10 = (vy1 && vx0) ? aw * dy * (1.f - dx)          : 0.f;
            float w11 = (vy1 && vx1) ? aw * dy * dx                  : 0.f;

            int xi0 = min(max(x0, 0), W - 1);
            int xi1 = min(max(x0 + 1, 0), W - 1);
            int yi0 = min(max(y0, 0), H - 1);
            int yi1 = min(max(y0 + 1, 0), H - 1);

            __half2 h00 = __float2half2_rn(w00);
            __half2 h01 = __float2half2_rn(w01);
            __half2 h10 = __float2half2_rn(w10);
            __half2 h11 = __float2half2_rn(w11);
            uint4 wq;
            wq.x = *reinterpret_cast<uint32_t*>(&h00);
            wq.y = *reinterpret_cast<uint32_t*>(&h01);
            wq.z = *reinterpret_cast<uint32_t*>(&h10);
            wq.w = *reinterpret_cast<uint32_t*>(&h11);
            smw[qi][tid] = wq;
            smi[qi][tid] = make_uint4((uint32_t)(st + yi0 * W + xi0) << 9,
                                      (uint32_t)(st + yi0 * W + xi1) << 9,
                                      (uint32_t)(st + yi1 * W + xi0) << 9,
                                      (uint32_t)(st + yi1 * W + xi1) << 9);
        }
    }
    __syncthreads();

    const int qi = tid >> 6;
    const int r  = tid & 63;
    const int m  = r >> 3;       // head 0..7
    const int c4 = r & 7;        // channel group: 4 channels
    const int s  = s0 + qi;
    if (s >= S_TOT) return;

    const char* vb = (const char*)val16 + (size_t)(m * 32 + c4 * 4) * sizeof(__half);
    float a0 = 0.f, a1 = 0.f, a2 = 0.f, a3 = 0.f;
    #pragma unroll
    for (int p = 0; p < 16; p++) {
        uint4 wq = smw[qi][m * 16 + p];
        uint4 ii = smi[qi][m * 16 + p];
        uint2 u0 = *reinterpret_cast<const uint2*>(vb + ii.x);
        uint2 u1 = *reinterpret_cast<const uint2*>(vb + ii.y);
        uint2 u2 = *reinterpret_cast<const uint2*>(vb + ii.z);
        uint2 u3 = *reinterpret_cast<const uint2*>(vb + ii.w);
        __half2 w0 = *reinterpret_cast<__half2*>(&wq.x);
        __half2 w1 = *reinterpret_cast<__half2*>(&wq.y);
        __half2 w2 = *reinterpret_cast<__half2*>(&wq.z);
        __half2 w3 = *reinterpret_cast<__half2*>(&wq.w);
        __half2 lo = __hmul2(w0, *reinterpret_cast<__half2*>(&u0.x));
        lo = __hfma2(w1, *reinterpret_cast<__half2*>(&u1.x), lo);
        lo = __hfma2(w2, *reinterpret_cast<__half2*>(&u2.x), lo);
        lo = __hfma2(w3, *reinterpret_cast<__half2*>(&u3.x), lo);
        __half2 hi = __hmul2(w0, *reinterpret_cast<__half2*>(&u0.y));
        hi = __hfma2(w1, *reinterpret_cast<__half2*>(&u1.y), hi);
        hi = __hfma2(w2, *reinterpret_cast<__half2*>(&u2.y), hi);
        hi = __hfma2(w3, *reinterpret_cast<__half2*>(&u3.y), hi);
        float2 flo = __half22float2(lo);
        float2 fhi = __half22float2(hi);
        a0 += flo.x; a1 += flo.y; a2 += fhi.x; a3 += fhi.y;
    }
    __half2 o0 = __floats2half2_rn(a0, a1);
    __half2 o1 = __floats2half2_rn(a2, a3);
    uint2 ov;
    ov.x = *reinterpret_cast<uint32_t*>(&o0);
    ov.y = *reinterpret_cast<uint32_t*>(&o1);
    *reinterpret_cast<uint2*>(out16 + (size_t)s * 256 + m * 32 + c4 * 4) = ov;
}

// ---------------- residual + split-K partials + LayerNorm (in place) ------
__device__ __forceinline__ float block_sum(float v) {
    __shared__ float sh[8];
    int lane = threadIdx.x & 31, wid = threadIdx.x >> 5;
    #pragma unroll
    for (int o = 16; o > 0; o >>= 1) v += __shfl_xor_sync(0xffffffffu, v, o);
    if (lane == 0) sh[wid] = v;
    __syncthreads();
    if (wid == 0) {
        float t = (lane < 8) ? sh[lane] : 0.f;
        #pragma unroll
        for (int o = 4; o > 0; o >>= 1) t += __shfl_xor_sync(0xffffffffu, t, o);
        if (lane == 0) sh[0] = t;
    }
    __syncthreads();
    float r = sh[0];
    __syncthreads();
    return r;
}

// x = LN(x + p0 + p1); optional fp16 copies: x16 = h(x), q16 = h(x + pos)
__global__ __launch_bounds__(256) void add3_ln_kernel(
    float* __restrict__ x, const float* __restrict__ p0, const float* __restrict__ p1,
    const float* __restrict__ g, const float* __restrict__ b,
    __half* __restrict__ x16, const float* __restrict__ pos, __half* __restrict__ q16)
{
    int s = blockIdx.x;
    int t = threadIdx.x;
    size_t i = (size_t)s * 256 + t;
    float v = x[i] + (p0[i] + p1[i]);
    float mean = block_sum(v) * (1.f / 256.f);
    float d = v - mean;
    float var = block_sum(d * d) * (1.f / 256.f);
    float inv = rsqrtf(var + 1e-5f);
    float r = d * inv * g[t] + b[t];
    x[i] = r;
    if (x16) x16[i] = __float2half(r);
    if (q16) q16[i] = __float2half(r + pos[i]);
}

// ---------------- launch --------------------------------------------------
extern "C" void kernel_launch(void* const* d_in, const int* in_sizes, int n_in,
                              void* d_out, int out_size) {
    const float* src    = (const float*)d_in[0];
    const float* pos    = (const float*)d_in[1];
    const float* vr     = (const float*)d_in[2];
    const float* W_off  = (const float*)d_in[6];
    const float* b_off  = (const float*)d_in[7];
    const float* W_attn = (const float*)d_in[8];
    const float* b_attn = (const float*)d_in[9];
    const float* W_val  = (const float*)d_in[10];
    const float* b_val  = (const float*)d_in[11];
    const float* W_out  = (const float*)d_in[12];
    const float* b_out  = (const float*)d_in[13];
    const float* ln1_g  = (const float*)d_in[14];
    const float* ln1_b  = (const float*)d_in[15];
    const float* W_ff1  = (const float*)d_in[16];
    const float* b_ff1  = (const float*)d_in[17];
    const float* W_ff2  = (const float*)d_in[18];
    const float* b_ff2  = (const float*)d_in[19];
    const float* ln2_g  = (const float*)d_in[20];
    const float* ln2_b  = (const float*)d_in[21];

    float* x = (float*)d_out;   // running activation, ends as the output

    float *off, *attn, *tmp, *tmp2;
    __half *v16, *x16, *q16, *s16, *f16, *w16;
    cudaGetSymbolAddress((void**)&off,  g_off);
    cudaGetSymbolAddress((void**)&attn, g_attn);
    cudaGetSymbolAddress((void**)&tmp,  g_tmp);
    cudaGetSymbolAddress((void**)&tmp2, g_tmp2);
    cudaGetSymbolAddress((void**)&v16,  g_v16);
    cudaGetSymbolAddress((void**)&x16,  g_x16);
    cudaGetSymbolAddress((void**)&q16,  g_q16);
    cudaGetSymbolAddress((void**)&s16,  g_s16);
    cudaGetSymbolAddress((void**)&f16,  g_f16);
    cudaGetSymbolAddress((void**)&w16,  g_w16);

    const int S = S_TOT;
    const int MB = 121;                       // ceil(7681/64)
    const dim3 g3(5, MB);                     // fused val/off/attn: 605 blocks
    const dim3 gsk(2, MB, 2);                 // split-K=2, N=256: 484 blocks
    const dim3 gff1(8, MB);                   // ff1: 968 blocks
    const int MS = (S + 1) / 2;               // msda: 2 queries per block

    // fused weight conversion: all 6 weights x 3 layers, one launch
    WC wc;
    wc.src[0] = W_val;  wc.K[0] = 256;  wc.N[0] = 256;  wc.ooff[0] = OFF_VAL;
    wc.src[1] = W_off;  wc.K[1] = 256;  wc.N[1] = 256;  wc.ooff[1] = OFF_OFF;
    wc.src[2] = W_attn; wc.K[2] = 256;  wc.N[2] = 128;  wc.ooff[2] = OFF_ATTN;
    wc.src[3] = W_out;  wc.K[3] = 256;  wc.N[3] = 256;  wc.ooff[3] = OFF_OUT;
    wc.src[4] = W_ff1;  wc.K[4] = 256;  wc.N[4] = 1024; wc.ooff[4] = OFF_FF1;
    wc.src[5] = W_ff2;  wc.K[5] = 1024; wc.N[5] = 256;  wc.ooff[5] = OFF_FF2;
    wc.cum[0] = 0;
    for (int g = 0; g < 6; g++)
        wc.cum[g + 1] = wc.cum[g] + (wc.K[g] / 32) * (wc.N[g] / 32);
    wcvt_all_kernel<<<dim3(wc.cum[6], 1, 3), 256>>>(wc, w16);

    copy2_kernel<<<S, 256>>>(x, x16, q16, src, pos);

    for (int l = 0; l < 3; l++) {
        const __half* wl = w16 + (size_t)l * W_LSTR;

        MG3 mg;
        mg.A[0] = x16; mg.B[0] = wl + OFF_VAL;  mg.bias[0] = b_val  + l * 256; mg.C[0] = nullptr; mg.C16[0] = v16;     mg.N[0] = 256;
        mg.A[1] = q16; mg.B[1] = wl + OFF_OFF;  mg.bias[1] = b_off  + l * 256; mg.C[1] = off;     mg.C16[1] = nullptr; mg.N[1] = 256;
        mg.A[2] = q16; mg.B[2] = wl + OFF_ATTN; mg.bias[2] = b_attn + l * 128; mg.C[2] = attn;    mg.C16[2] = nullptr; mg.N[2] = 128;
        gemm3_kernel<<<g3, 256>>>(mg, S, 256);

        msda_kernel<<<MS, 128>>>(v16, off, attn, vr, s16);

        gemm_sk2_kernel<<<gsk, 256>>>(s16, wl + OFF_OUT, b_out + l * 256,
                                      tmp, tmp2, S, 256, 256);
        add3_ln_kernel<<<S, 256>>>(x, tmp, tmp2, ln1_g + l * 256, ln1_b + l * 256,
                                   x16, nullptr, nullptr);

        gemm_ff1_kernel<<<gff1, 256>>>(x16, wl + OFF_FF1, b_ff1 + l * 1024,
                                       f16, S, 1024, 256);
        gemm_sk2_kernel<<<gsk, 256>>>(f16, wl + OFF_FF2, b_ff2 + l * 256,
                                      tmp, tmp2, S, 256, 1024);
        add3_ln_kernel<<<S, 256>>>(x, tmp, tmp2, ln2_g + l * 256, ln2_b + l * 256,
                                   (l < 2) ? x16 : nullptr,
                                   (l < 2) ? pos : nullptr,
                                   (l < 2) ? q16 : nullptr);
    }
}

// round 17
// speedup vs baseline: 1.1249x; 1.1249x over previous
#include <cuda_runtime.h>
#include <cuda_fp16.h>
#include <math.h>
#include <stdint.h>

#define S_TOT 7681
#define C_DIM 256

// ---------------- scratch (static device globals; no allocation) ----------
__device__ float  g_off [S_TOT * C_DIM];
__device__ float  g_attn[S_TOT * 128];
__device__ float  g_tmp [S_TOT * C_DIM];
__device__ float  g_tmp2[S_TOT * C_DIM];
__device__ __half g_v16 [S_TOT * C_DIM];
__device__ __half g_x16 [S_TOT * C_DIM];
__device__ __half g_q16 [S_TOT * C_DIM];
__device__ __half g_s16 [S_TOT * C_DIM];
__device__ __half g_f16 [S_TOT * 1024];
// fp16 transposed weights, per-layer stride 753664:
// val@0, off@65536, attn@131072, out@163840, ff1@229376, ff2@491520
__device__ __half g_w16 [3 * 753664];

#define OFF_VAL  0
#define OFF_OFF  65536
#define OFF_ATTN 131072
#define OFF_OUT  163840
#define OFF_FF1  229376
#define OFF_FF2  491520
#define W_LSTR   753664

__constant__ int c_H [4] = {76, 38, 19, 10};
__constant__ int c_W [4] = {76, 38, 19, 10};
__constant__ int c_ST[4] = {0, 5776, 7220, 7581};

// ---------------- fused weight convert + transpose ------------------------
struct WC {
    const float* src[6];
    int K[6], N[6], ooff[6];
    int cum[7];                 // cumulative 32x32 tile counts
};

__global__ __launch_bounds__(256) void wcvt_all_kernel(WC wc, __half* w16)
{
    __shared__ float t[32][33];
    int b = blockIdx.x;
    int g = 0;
    while (b >= wc.cum[g + 1]) g++;
    int tile = b - wc.cum[g];
    const int K = wc.K[g], N = wc.N[g];
    const int ntiles = N >> 5;
    const int k0 = (tile / ntiles) * 32;
    const int n0 = (tile % ntiles) * 32;
    const float* inl = wc.src[g] + (size_t)blockIdx.z * (size_t)K * N;
    __half* outl = w16 + (size_t)blockIdx.z * W_LSTR + wc.ooff[g];
    int tx = threadIdx.x & 31, ty = threadIdx.x >> 5;
    #pragma unroll
    for (int i = ty; i < 32; i += 8)
        t[i][tx] = inl[(size_t)(k0 + i) * N + n0 + tx];
    __syncthreads();
    #pragma unroll
    for (int i = ty; i < 32; i += 8)
        outl[(size_t)(n0 + i) * K + k0 + tx] = __float2half(t[tx][i]);
}

// ---------------- init: x = src; x16 = h(src); q16 = h(src + pos) ---------
__global__ __launch_bounds__(256) void copy2_kernel(
    float* __restrict__ x, __half* __restrict__ x16, __half* __restrict__ q16,
    const float* __restrict__ src, const float* __restrict__ pos)
{
    int i = blockIdx.x * 256 + threadIdx.x;
    float v = src[i];
    x[i] = v;
    x16[i] = __float2half(v);
    q16[i] = __float2half(v + pos[i]);
}

// ---------------- fp16 tensor-core GEMM primitives ------------------------
__device__ __forceinline__ void cp16(uint32_t s, const void* g) {
    asm volatile("cp.async.cg.shared.global [%0], [%1], 16;" :: "r"(s), "l"(g) : "memory");
}

__device__ __forceinline__ uint32_t smem_u32(const void* p) {
    return (uint32_t)__cvta_generic_to_shared(p);
}

__device__ __forceinline__ void ldsm4(uint32_t r[4], uint32_t addr) {
    asm volatile("ldmatrix.sync.aligned.m8n8.x4.shared.b16 {%0,%1,%2,%3}, [%4];"
                 : "=r"(r[0]), "=r"(r[1]), "=r"(r[2]), "=r"(r[3]) : "r"(addr));
}

__device__ __forceinline__ void mma16(float c[4], const uint32_t a[4], const uint32_t b[2]) {
    asm volatile(
        "mma.sync.aligned.m16n8k16.row.col.f32.f16.f16.f32 "
        "{%0,%1,%2,%3}, {%4,%5,%6,%7}, {%8,%9}, {%0,%1,%2,%3};"
        : "+f"(c[0]), "+f"(c[1]), "+f"(c[2]), "+f"(c[3])
        : "r"(a[0]), "r"(a[1]), "r"(a[2]), "r"(a[3]), "r"(b[0]), "r"(b[1]));
}

// Core mainloop + epilogue. BM=64 x BN=128, 256 threads (8 warps: 2M x 4N),
// warp tile 32x32, BK=32, 3-stage cp.async, ldmatrix fragment loads.
template<int RELU, int OUTH>
__device__ __forceinline__ void gemm_body(
    const __half* __restrict__ A, const __half* __restrict__ B,
    const float* __restrict__ bias, float* __restrict__ C, __half* __restrict__ C16,
    int M, int N, int K, int lda, int ldb, int m0, int n0, int use_bias,
    __half (*As)[64][40], __half (*Bs)[128][40])
{
    constexpr int BK = 32;
    constexpr int NT = 4;

    const int tid  = threadIdx.x;
    const int lane = tid & 31;
    const int wid  = tid >> 5;
    const int wm   = wid & 1;    // warp row 0..1
    const int wn   = wid >> 1;   // warp col 0..3

    float acc[2][NT][4];
    #pragma unroll
    for (int mt = 0; mt < 2; mt++)
        #pragma unroll
        for (int nt = 0; nt < NT; nt++)
            #pragma unroll
            for (int j = 0; j < 4; j++) acc[mt][nt][j] = 0.f;

    auto prefetch = [&](int buf, int k0) {
        {   // A: 64 rows x 64B
            int r = tid >> 2, c = (tid & 3) * 8;
            int gm = m0 + r; if (gm > M - 1) gm = M - 1;
            cp16(smem_u32(&As[buf][r][c]), A + (size_t)gm * lda + k0 + c);
        }
        #pragma unroll
        for (int i = 0; i < 2; i++) {   // B: 128 rows x 64B
            int f = tid + i * 256;
            int r = f >> 2, c = (f & 3) * 8;
            cp16(smem_u32(&Bs[buf][r][c]), B + (size_t)(n0 + r) * ldb + k0 + c);
        }
        asm volatile("cp.async.commit_group;" ::: "memory");
    };

    prefetch(0, 0);
    if (BK < K) prefetch(1, BK);
    else        asm volatile("cp.async.commit_group;" ::: "memory");

    const int tr = lane & 7;     // row within 8x8 tile
    const int tq = lane >> 3;    // tile index 0..3

    int buf = 0;
    for (int k0 = 0; k0 < K; k0 += BK) {
        if (k0 + BK < K) asm volatile("cp.async.wait_group 1;" ::: "memory");
        else             asm volatile("cp.async.wait_group 0;" ::: "memory");
        __syncthreads();

        if (k0 + 2 * BK < K) {
            int nb = buf + 2; if (nb >= 3) nb -= 3;
            prefetch(nb, k0 + 2 * BK);
        }

        #pragma unroll
        for (int kc = 0; kc < BK; kc += 16) {
            uint32_t afr[2][4];
            #pragma unroll
            for (int mt = 0; mt < 2; mt++) {
                int row = wm * 32 + mt * 16 + tr + ((tq & 1) ? 8 : 0);
                int col = kc + ((tq >= 2) ? 8 : 0);
                ldsm4(afr[mt], smem_u32(&As[buf][row][col]));
            }
            uint32_t bfr[NT][2];
            #pragma unroll
            for (int j = 0; j < 2; j++) {
                int nrow = wn * 32 + j * 16 + tr + ((tq >= 2) ? 8 : 0);
                int col  = kc + ((tq & 1) ? 8 : 0);
                uint32_t r[4];
                ldsm4(r, smem_u32(&Bs[buf][nrow][col]));
                bfr[2 * j][0] = r[0]; bfr[2 * j][1] = r[1];
                bfr[2 * j + 1][0] = r[2]; bfr[2 * j + 1][1] = r[3];
            }
            #pragma unroll
            for (int mt = 0; mt < 2; mt++)
                #pragma unroll
                for (int nt = 0; nt < NT; nt++)
                    mma16(acc[mt][nt], afr[mt], bfr[nt]);
        }
        buf++; if (buf >= 3) buf = 0;
    }

    #pragma unroll
    for (int mt = 0; mt < 2; mt++) {
        int gm = m0 + wm * 32 + mt * 16 + (lane >> 2);
        #pragma unroll
        for (int nt = 0; nt < NT; nt++) {
            int gn = n0 + wn * 32 + nt * 8 + 2 * (lane & 3);
            float b0 = 0.f, b1 = 0.f;
            if (use_bias) { b0 = bias[gn]; b1 = bias[gn + 1]; }
            float v0 = acc[mt][nt][0] + b0, v1 = acc[mt][nt][1] + b1;
            float v2 = acc[mt][nt][2] + b0, v3 = acc[mt][nt][3] + b1;
            if (RELU) {
                v0 = fmaxf(v0, 0.f); v1 = fmaxf(v1, 0.f);
                v2 = fmaxf(v2, 0.f); v3 = fmaxf(v3, 0.f);
            }
            if (OUTH) {
                if (gm < M)
                    *reinterpret_cast<__half2*>(C16 + (size_t)gm * N + gn) =
                        __floats2half2_rn(v0, v1);
                if (gm + 8 < M)
                    *reinterpret_cast<__half2*>(C16 + (size_t)(gm + 8) * N + gn) =
                        __floats2half2_rn(v2, v3);
            } else {
                if (gm < M)
                    *reinterpret_cast<float2*>(C + (size_t)gm * N + gn) = make_float2(v0, v1);
                if (gm + 8 < M)
                    *reinterpret_cast<float2*>(C + (size_t)(gm + 8) * N + gn) = make_float2(v2, v3);
            }
        }
    }
}

// ff1: C16 = relu(A@B + bias) in fp16
__global__ __launch_bounds__(256) void gemm_ff1_kernel(
    const __half* __restrict__ A, const __half* __restrict__ B,
    const float* __restrict__ bias, __half* __restrict__ C16,
    int M, int N, int K)
{
    __shared__ __half As[3][64][40];
    __shared__ __half Bs[3][128][40];
    gemm_body<1, 1>(A, B, bias, nullptr, C16, M, N, K, K, K,
                    blockIdx.y * 64, blockIdx.x * 128, 1, As, Bs);
}

// Split-K=2 GEMM, one launch: kz=0 -> C0 (+bias), kz=1 -> C1.
__global__ __launch_bounds__(256) void gemm_sk2_kernel(
    const __half* __restrict__ A, const __half* __restrict__ B,
    const float* __restrict__ bias, float* __restrict__ C0, float* __restrict__ C1,
    int M, int N, int Kfull)
{
    __shared__ __half As[3][64][40];
    __shared__ __half Bs[3][128][40];
    const int kz = blockIdx.z;
    const int Kh = Kfull >> 1;
    gemm_body<0, 0>(A + (size_t)kz * Kh, B + (size_t)kz * Kh,
                    bias, kz ? C1 : C0, nullptr, M, N, Kh, Kfull, Kfull,
                    blockIdx.y * 64, blockIdx.x * 128, kz == 0, As, Bs);
}

// Fused val/off/attn: 5 N-tiles (val:2 -> fp16 out, off:2, attn:1) x 121 M-blocks.
struct MG3 {
    const __half* A[3];
    const __half* B[3];
    const float* bias[3];
    float* C[3];
    __half* C16[3];
    int N[3];
};

__global__ __launch_bounds__(256) void gemm3_kernel(MG3 mg, int M, int K)
{
    __shared__ __half As[3][64][40];
    __shared__ __half Bs[3][128][40];
    const int bx  = blockIdx.x;                       // 0..4
    const int gid = (bx < 2) ? 0 : (bx < 4) ? 1 : 2;
    const int nb  = (bx == 1 || bx == 3) ? 1 : 0;
    if (gid == 0)
        gemm_body<0, 1>(mg.A[0], mg.B[0], mg.bias[0], nullptr, mg.C16[0],
                        M, mg.N[0], K, K, K, blockIdx.y * 64, nb * 128, 1, As, Bs);
    else
        gemm_body<0, 0>(mg.A[gid], mg.B[gid], mg.bias[gid], mg.C[gid], nullptr,
                        M, mg.N[gid], K, K, K, blockIdx.y * 64, nb * 128, 1, As, Bs);
}

// ---------------- MSDA: metadata + half2 gather, one 128-thread block/s ---
// (round-14 version: fastest measured at 26.1 us)
__global__ __launch_bounds__(128) void msda_kernel(
    const __half* __restrict__ val16, const float* __restrict__ off,
    const float* __restrict__ attn, const float* __restrict__ vr,
    __half* __restrict__ out16)
{
    const unsigned FULL = 0xffffffffu;
    const int s   = blockIdx.x;
    const int tid = threadIdx.x;

    __shared__ uint4 smw[128];   // per (m,p): 4 corner weights as broadcast half2
    __shared__ uint4 smi[128];   // per (m,p): 4 row byte-offsets (idx*512, fp16 rows)

    {
        const int m   = tid >> 4;
        const int p   = tid & 15;       // p = lvl*4 + pt
        const int lvl = p >> 2;
        const int pt  = p & 3;

        float logit = attn[(size_t)s * 128 + m * 16 + p];
        float mx = logit;
        #pragma unroll
        for (int o = 8; o > 0; o >>= 1) mx = fmaxf(mx, __shfl_xor_sync(FULL, mx, o));
        float e = expf(logit - mx);
        float sum = e;
        #pragma unroll
        for (int o = 8; o > 0; o >>= 1) sum += __shfl_xor_sync(FULL, sum, o);
        float aw = e / sum;

        int lvlS = (s >= 7581) ? 3 : (s >= 7220) ? 2 : (s >= 5776) ? 1 : 0;
        int idxS = s - c_ST[lvlS];
        int Ws = c_W[lvlS], Hs = c_H[lvlS];
        int rowS = idxS / Ws, colS = idxS - rowS * Ws;
        float bx = (colS + 0.5f) / (vr[lvlS * 2 + 0] * (float)Ws);
        float by = (rowS + 0.5f) / (vr[lvlS * 2 + 1] * (float)Hs);

        const int H = c_H[lvl], W = c_W[lvl], st = c_ST[lvl];
        float refx = bx * vr[lvl * 2 + 0];
        float refy = by * vr[lvl * 2 + 1];
        float ox = off[(size_t)s * 256 + m * 32 + lvl * 8 + pt * 2 + 0];
        float oy = off[(size_t)s * 256 + m * 32 + lvl * 8 + pt * 2 + 1];

        // match reference arithmetic order
        float lx = refx + ox / (float)W;
        float ly = refy + oy / (float)H;
        float x = lx * (float)W - 0.5f;
        float y = ly * (float)H - 0.5f;
        float x0f = floorf(x), y0f = floorf(y);
        int x0 = (int)x0f, y0 = (int)y0f;
        float dx = x - x0f, dy = y - y0f;

        bool vx0 = (x0 >= 0) & (x0 < W);
        bool vx1 = (x0 + 1 >= 0) & (x0 + 1 < W);
        bool vy0 = (y0 >= 0) & (y0 < H);
        bool vy1 = (y0 + 1 >= 0) & (y0 + 1 < H);

        float w00 = (vy0 && vx0) ? aw * (1.f - dy) * (1.f - dx) : 0.f;
        float w01 = (vy0 && vx1) ? aw * (1.f - dy) * dx          : 0.f;
        float w10 = (vy1 && vx0) ? aw * dy * (1.f - dx)          : 0.f;
        float w11 = (vy1 && vx1) ? aw * dy * dx                  : 0.f;

        int xi0 = min(max(x0, 0), W - 1);
        int xi1 = min(max(x0 + 1, 0), W - 1);
        int yi0 = min(max(y0, 0), H - 1);
        int yi1 = min(max(y0 + 1, 0), H - 1);

        __half2 h00 = __float2half2_rn(w00);
        __half2 h01 = __float2half2_rn(w01);
        __half2 h10 = __float2half2_rn(w10);
        __half2 h11 = __float2half2_rn(w11);
        uint4 wq;
        wq.x = *reinterpret_cast<uint32_t*>(&h00);
        wq.y = *reinterpret_cast<uint32_t*>(&h01);
        wq.z = *reinterpret_cast<uint32_t*>(&h10);
        wq.w = *reinterpret_cast<uint32_t*>(&h11);
        smw[tid] = wq;
        smi[tid] = make_uint4((uint32_t)(st + yi0 * W + xi0) << 9,
                              (uint32_t)(st + yi0 * W + xi1) << 9,
                              (uint32_t)(st + yi1 * W + xi0) << 9,
                              (uint32_t)(st + yi1 * W + xi1) << 9);
    }
    __syncthreads();

    // gather: 16 threads per head, each handles 2 channels (half2 loads,
    // fp16 4-corner interp, fp32 accumulation across the 16 points)
    const int m  = tid >> 4;
    const int c2 = tid & 15;
    const char* vb = (const char*)val16 + (size_t)(m * 32 + c2 * 2) * sizeof(__half);
    float accx = 0.f, accy = 0.f;
    #pragma unroll
    for (int p = 0; p < 16; p++) {
        uint4 wq = smw[m * 16 + p];
        uint4 ii = smi[m * 16 + p];
        __half2 v0 = *reinterpret_cast<const __half2*>(vb + ii.x);
        __half2 v1 = *reinterpret_cast<const __half2*>(vb + ii.y);
        __half2 v2 = *reinterpret_cast<const __half2*>(vb + ii.z);
        __half2 v3 = *reinterpret_cast<const __half2*>(vb + ii.w);
        __half2 sacc = __hmul2(*reinterpret_cast<__half2*>(&wq.x), v0);
        sacc = __hfma2(*reinterpret_cast<__half2*>(&wq.y), v1, sacc);
        sacc = __hfma2(*reinterpret_cast<__half2*>(&wq.z), v2, sacc);
        sacc = __hfma2(*reinterpret_cast<__half2*>(&wq.w), v3, sacc);
        float2 sf = __half22float2(sacc);
        accx += sf.x; accy += sf.y;
    }
    *reinterpret_cast<__half2*>(out16 + (size_t)s * 256 + m * 32 + c2 * 2) =
        __floats2half2_rn(accx, accy);
}

// ---------------- warp-per-row residual + partials + LayerNorm ------------
// 8 rows per 256-thread block; lane holds 8 channels (2 x float4); no BARs.
__global__ __launch_bounds__(256) void add3_ln_kernel(
    float* __restrict__ x, const float* __restrict__ p0, const float* __restrict__ p1,
    const float* __restrict__ g, const float* __restrict__ b,
    __half* __restrict__ x16, const float* __restrict__ pos, __half* __restrict__ q16)
{
    const unsigned FULL = 0xffffffffu;
    const int row  = blockIdx.x * 8 + (threadIdx.x >> 5);
    const int lane = threadIdx.x & 31;
    if (row >= S_TOT) return;
    const size_t base = (size_t)row * 256;

    float v[2][4];
    float s = 0.f;
    #pragma unroll
    for (int j = 0; j < 2; j++) {
        const int c = j * 128 + lane * 4;
        float4 a  = *reinterpret_cast<const float4*>(x  + base + c);
        float4 q0 = *reinterpret_cast<const float4*>(p0 + base + c);
        float4 q1 = *reinterpret_cast<const float4*>(p1 + base + c);
        v[j][0] = a.x + (q0.x + q1.x);
        v[j][1] = a.y + (q0.y + q1.y);
        v[j][2] = a.z + (q0.z + q1.z);
        v[j][3] = a.w + (q0.w + q1.w);
        s += (v[j][0] + v[j][1]) + (v[j][2] + v[j][3]);
    }
    #pragma unroll
    for (int o = 16; o > 0; o >>= 1) s += __shfl_xor_sync(FULL, s, o);
    const float mean = s * (1.f / 256.f);

    float vs = 0.f;
    #pragma unroll
    for (int j = 0; j < 2; j++)
        #pragma unroll
        for (int k = 0; k < 4; k++) {
            float d = v[j][k] - mean;
            v[j][k] = d;
            vs += d * d;
        }
    #pragma unroll
    for (int o = 16; o > 0; o >>= 1) vs += __shfl_xor_sync(FULL, vs, o);
    const float inv = rsqrtf(vs * (1.f / 256.f) + 1e-5f);

    #pragma unroll
    for (int j = 0; j < 2; j++) {
        const int c = j * 128 + lane * 4;
        float4 gg = *reinterpret_cast<const float4*>(g + c);
        float4 bb = *reinterpret_cast<const float4*>(b + c);
        float r0 = v[j][0] * inv * gg.x + bb.x;
        float r1 = v[j][1] * inv * gg.y + bb.y;
        float r2 = v[j][2] * inv * gg.z + bb.z;
        float r3 = v[j][3] * inv * gg.w + bb.w;
        *reinterpret_cast<float4*>(x + base + c) = make_float4(r0, r1, r2, r3);
        if (x16) {
            __half2 h0 = __floats2half2_rn(r0, r1);
            __half2 h1 = __floats2half2_rn(r2, r3);
            uint2 hv;
            hv.x = *reinterpret_cast<uint32_t*>(&h0);
            hv.y = *reinterpret_cast<uint32_t*>(&h1);
            *reinterpret_cast<uint2*>(x16 + base + c) = hv;
        }
        if (q16) {
            float4 pp = *reinterpret_cast<const float4*>(pos + base + c);
            __half2 h0 = __floats2half2_rn(r0 + pp.x, r1 + pp.y);
            __half2 h1 = __floats2half2_rn(r2 + pp.z, r3 + pp.w);
            uint2 hv;
            hv.x = *reinterpret_cast<uint32_t*>(&h0);
            hv.y = *reinterpret_cast<uint32_t*>(&h1);
            *reinterpret_cast<uint2*>(q16 + base + c) = hv;
        }
    }
}

// ---------------- launch --------------------------------------------------
extern "C" void kernel_launch(void* const* d_in, const int* in_sizes, int n_in,
                              void* d_out, int out_size) {
    const float* src    = (const float*)d_in[0];
    const float* pos    = (const float*)d_in[1];
    const float* vr     = (const float*)d_in[2];
    const float* W_off  = (const float*)d_in[6];
    const float* b_off  = (const float*)d_in[7];
    const float* W_attn = (const float*)d_in[8];
    const float* b_attn = (const float*)d_in[9];
    const float* W_val  = (const float*)d_in[10];
    const float* b_val  = (const float*)d_in[11];
    const float* W_out  = (const float*)d_in[12];
    const float* b_out  = (const float*)d_in[13];
    const float* ln1_g  = (const float*)d_in[14];
    const float* ln1_b  = (const float*)d_in[15];
    const float* W_ff1  = (const float*)d_in[16];
    const float* b_ff1  = (const float*)d_in[17];
    const float* W_ff2  = (const float*)d_in[18];
    const float* b_ff2  = (const float*)d_in[19];
    const float* ln2_g  = (const float*)d_in[20];
    const float* ln2_b  = (const float*)d_in[21];

    float* x = (float*)d_out;   // running activation, ends as the output

    float *off, *attn, *tmp, *tmp2;
    __half *v16, *x16, *q16, *s16, *f16, *w16;
    cudaGetSymbolAddress((void**)&off,  g_off);
    cudaGetSymbolAddress((void**)&attn, g_attn);
    cudaGetSymbolAddress((void**)&tmp,  g_tmp);
    cudaGetSymbolAddress((void**)&tmp2, g_tmp2);
    cudaGetSymbolAddress((void**)&v16,  g_v16);
    cudaGetSymbolAddress((void**)&x16,  g_x16);
    cudaGetSymbolAddress((void**)&q16,  g_q16);
    cudaGetSymbolAddress((void**)&s16,  g_s16);
    cudaGetSymbolAddress((void**)&f16,  g_f16);
    cudaGetSymbolAddress((void**)&w16,  g_w16);

    const int S = S_TOT;
    const int MB = 121;                       // ceil(7681/64)
    const dim3 g3(5, MB);                     // fused val/off/attn: 605 blocks
    const dim3 gsk(2, MB, 2);                 // split-K=2, N=256: 484 blocks
    const dim3 gff1(8, MB);                   // ff1: 968 blocks
    const int LNB = (S + 7) / 8;              // warp-per-row LN: 961 blocks

    // fused weight conversion: all 6 weights x 3 layers, one launch
    WC wc;
    wc.src[0] = W_val;  wc.K[0] = 256;  wc.N[0] = 256;  wc.ooff[0] = OFF_VAL;
    wc.src[1] = W_off;  wc.K[1] = 256;  wc.N[1] = 256;  wc.ooff[1] = OFF_OFF;
    wc.src[2] = W_attn; wc.K[2] = 256;  wc.N[2] = 128;  wc.ooff[2] = OFF_ATTN;
    wc.src[3] = W_out;  wc.K[3] = 256;  wc.N[3] = 256;  wc.ooff[3] = OFF_OUT;
    wc.src[4] = W_ff1;  wc.K[4] = 256;  wc.N[4] = 1024; wc.ooff[4] = OFF_FF1;
    wc.src[5] = W_ff2;  wc.K[5] = 1024; wc.N[5] = 256;  wc.ooff[5] = OFF_FF2;
    wc.cum[0] = 0;
    for (int g = 0; g < 6; g++)
        wc.cum[g + 1] = wc.cum[g] + (wc.K[g] / 32) * (wc.N[g] / 32);
    wcvt_all_kernel<<<dim3(wc.cum[6], 1, 3), 256>>>(wc, w16);

    copy2_kernel<<<S, 256>>>(x, x16, q16, src, pos);

    for (int l = 0; l < 3; l++) {
        const __half* wl = w16 + (size_t)l * W_LSTR;

        MG3 mg;
        mg.A[0] = x16; mg.B[0] = wl + OFF_VAL;  mg.bias[0] = b_val  + l * 256; mg.C[0] = nullptr; mg.C16[0] = v16;     mg.N[0] = 256;
        mg.A[1] = q16; mg.B[1] = wl + OFF_OFF;  mg.bias[1] = b_off  + l * 256; mg.C[1] = off;     mg.C16[1] = nullptr; mg.N[1] = 256;
        mg.A[2] = q16; mg.B[2] = wl + OFF_ATTN; mg.bias[2] = b_attn + l * 128; mg.C[2] = attn;    mg.C16[2] = nullptr; mg.N[2] = 128;
        gemm3_kernel<<<g3, 256>>>(mg, S, 256);

        msda_kernel<<<S, 128>>>(v16, off, attn, vr, s16);

        gemm_sk2_kernel<<<gsk, 256>>>(s16, wl + OFF_OUT, b_out + l * 256,
                                      tmp, tmp2, S, 256, 256);
        add3_ln_kernel<<<LNB, 256>>>(x, tmp, tmp2, ln1_g + l * 256, ln1_b + l * 256,
                                     x16, nullptr, nullptr);

        gemm_ff1_kernel<<<gff1, 256>>>(x16, wl + OFF_FF1, b_ff1 + l * 1024,
                                       f16, S, 1024, 256);
        gemm_sk2_kernel<<<gsk, 256>>>(f16, wl + OFF_FF2, b_ff2 + l * 256,
                                      tmp, tmp2, S, 256, 1024);
        add3_ln_kernel<<<LNB, 256>>>(x, tmp, tmp2, ln2_g + l * 256, ln2_b + l * 256,
                                     (l < 2) ? x16 : nullptr,
                                     (l < 2) ? pos : nullptr,
                                     (l < 2) ? q16 : nullptr);
    }
}